// round 3
// baseline (speedup 1.0000x reference)
#include <cuda_runtime.h>
#include <cuda_bf16.h>

// Problem: video [B=8, C=3, T=32, H=224, W=224] fp32.
// reference = trilinear resize to (32, 240, 240) (T axis is identity since
// scale==1 with half-pixel centers), clip[0,1], then per-frame crop HxW at
// (shake_h[t], shake_w[t]).
// Fused form: out[b,c,t,y,x] = clamp-bilinear sample of frame (b,c,t) at
//   src_y = (y + shake_h[t] + 0.5) * (224/240) - 0.5
//   src_x = (x + shake_w[t] + 0.5) * (224/240) - 0.5
// jax's boundary weight renormalization for the linear kernel == coordinate
// clamping, so clamped bilinear is exact.

#define HH 224
#define WW 224
#define TT 32
#define NPLANES 768            // B*C*T = 8*3*32
#define SCALE_F (14.0f / 15.0f) // 224/240

__global__ __launch_bounds__(256) void shake_bilinear_kernel(
    const float* __restrict__ vid,
    const int*   __restrict__ sh,
    const int*   __restrict__ sw,
    float*       __restrict__ out)
{
    // One thread = 4 consecutive x outputs (float4 store).
    const int XQ = WW / 4; // 56
    int tid = blockIdx.x * blockDim.x + threadIdx.x;
    int x4 = tid % XQ;
    int r  = tid / XQ;
    int y  = r % HH;
    int p  = r / HH;            // plane index ((b*C + c)*T + t)
    if (p >= NPLANES) return;

    int t   = p & (TT - 1);
    int sht = __ldg(sh + t);
    int swt = __ldg(sw + t);

    // Vertical weights (shared by the 4 outputs)
    float sy  = ((float)(y + sht) + 0.5f) * SCALE_F - 0.5f;
    float fy0 = floorf(sy);
    float fy  = sy - fy0;
    int   y0  = (int)fy0;
    int   y0c = max(y0, 0);
    int   y1c = min(y0 + 1, HH - 1);

    const float* row0 = vid + ((long long)p * HH + y0c) * WW;
    const float* row1 = vid + ((long long)p * HH + y1c) * WW;

    float4 res;
    float* rp = (float*)&res;
    int xb = x4 * 4;

#pragma unroll
    for (int j = 0; j < 4; j++) {
        int   x   = xb + j;
        float sx  = ((float)(x + swt) + 0.5f) * SCALE_F - 0.5f;
        float fx0 = floorf(sx);
        float fx  = sx - fx0;
        int   x0  = (int)fx0;
        int   x0c = max(x0, 0);
        int   x1c = min(x0 + 1, WW - 1);

        float v00 = __ldg(row0 + x0c);
        float v01 = __ldg(row0 + x1c);
        float v10 = __ldg(row1 + x0c);
        float v11 = __ldg(row1 + x1c);

        float top = fmaf(fx, v01 - v00, v00);
        float bot = fmaf(fx, v11 - v10, v10);
        float v   = fmaf(fy, bot - top, top);
        rp[j] = fminf(fmaxf(v, 0.0f), 1.0f);
    }

    // Coalesced 16B store; W divisible by 4, buffer 16B-aligned.
    ((float4*)out)[tid] = res;
}

extern "C" void kernel_launch(void* const* d_in, const int* in_sizes, int n_in,
                              void* d_out, int out_size)
{
    const float* vid = (const float*)d_in[0];
    const int*   sh  = (const int*)d_in[1];
    const int*   sw  = (const int*)d_in[2];
    float*       out = (float*)d_out;

    long long total = (long long)NPLANES * HH * (WW / 4); // 9,633,792 threads
    int threads = 256;
    int blocks  = (int)((total + threads - 1) / threads);
    shake_bilinear_kernel<<<blocks, threads>>>(vid, sh, sw, out);
}

// round 4
// speedup vs baseline: 1.1644x; 1.1644x over previous
#include <cuda_runtime.h>
#include <cuda_bf16.h>

// video [B=8, C=3, T=32, H=224, W=224] fp32.
// out[b,c,t,y,x] = clip01( clamped-bilinear sample of frame (b,c,t) at
//   src = (coord + shake + 0.5) * (224/240) - 0.5 )
// (trilinear resize 224->240 has identity T axis; jax boundary weight
//  renormalization for the linear kernel == coordinate clamping.)
//
// R3: shared-memory row staging. One block = one plane x 16 output rows.
// 16 output rows need <= 16 consecutive source rows (15*14/15=14 span +1 tap).
// Stage them with coalesced float4 LDG, take all bilinear taps from LDS.

#define HH 224
#define WW 224
#define TT 32
#define NPLANES 768             // B*C*T
#define TILE_Y 16
#define TILES_PER_PLANE (HH / TILE_Y)   // 14
#define THREADS 224
#define SCALE_F (14.0f / 15.0f)

__global__ __launch_bounds__(THREADS) void shake_bilinear_smem_kernel(
    const float* __restrict__ vid,
    const int*   __restrict__ sh,
    const int*   __restrict__ sw,
    float*       __restrict__ out)
{
    __shared__ float srows[TILE_Y][WW];   // 16 x 224 fp32 = 14336 B

    int blk  = blockIdx.x;
    int tile = blk % TILES_PER_PLANE;
    int p    = blk / TILES_PER_PLANE;     // plane = (b*C + c)*T + t
    int t    = p & (TT - 1);
    int sht  = __ldg(sh + t);
    int swt  = __ldg(sw + t);
    int yb   = tile * TILE_Y;
    int tid  = threadIdx.x;

    // Base source row for this tile (may be -1 at the top edge).
    float sy0  = ((float)(yb + sht) + 0.5f) * SCALE_F - 0.5f;
    int   base = (int)floorf(sy0);

    // Stage 16 source rows, clamped at load time: srows[r] = vid row clamp(base+r).
    const float* plane = vid + (long long)p * (HH * WW);
#pragma unroll
    for (int k = 0; k < 4; k++) {
        int i = tid + k * THREADS;        // 0..895 over 16*56 float4s
        int r = i / (WW / 4);
        int c = i % (WW / 4);
        int srcr = min(max(base + r, 0), HH - 1);
        float4 v = *(const float4*)(plane + srcr * WW + c * 4);
        *(float4*)(&srows[r][c * 4]) = v;
    }
    __syncthreads();

    // Thread -> fixed x-quad, 4 y-rows strided by 4.
    int x4 = tid % (WW / 4);              // 0..55
    int yy = tid / (WW / 4);              // 0..3
    int xb = x4 * 4;

    // Horizontal weights once, reused for all 4 rows.
    float fx[4]; int xi0[4], xi1[4];
#pragma unroll
    for (int j = 0; j < 4; j++) {
        float sx  = ((float)(xb + j + swt) + 0.5f) * SCALE_F - 0.5f;
        float f0  = floorf(sx);
        fx[j]     = sx - f0;
        int   x0  = (int)f0;
        xi0[j] = max(x0, 0);
        xi1[j] = min(x0 + 1, WW - 1);
    }

    float4* outp = (float4*)(out + (long long)p * (HH * WW));
#pragma unroll
    for (int k = 0; k < 4; k++) {
        int   y   = yy + 4 * k;           // 0..15
        float sy  = ((float)(yb + y + sht) + 0.5f) * SCALE_F - 0.5f;
        float f0  = floorf(sy);
        float fy  = sy - f0;
        int   r0  = (int)f0 - base;       // in [0,14]; r0+1 <= 15 (clamped content)

        const float* R0 = srows[r0];
        const float* R1 = srows[r0 + 1];

        float4 res;
        float* rp = (float*)&res;
#pragma unroll
        for (int j = 0; j < 4; j++) {
            float v00 = R0[xi0[j]];
            float v01 = R0[xi1[j]];
            float v10 = R1[xi0[j]];
            float v11 = R1[xi1[j]];
            float top = fmaf(fx[j], v01 - v00, v00);
            float bot = fmaf(fx[j], v11 - v10, v10);
            float v   = fmaf(fy, bot - top, top);
            rp[j] = fminf(fmaxf(v, 0.0f), 1.0f);
        }
        outp[(yb + y) * (WW / 4) + x4] = res;
    }
}

extern "C" void kernel_launch(void* const* d_in, const int* in_sizes, int n_in,
                              void* d_out, int out_size)
{
    const float* vid = (const float*)d_in[0];
    const int*   sh  = (const int*)d_in[1];
    const int*   sw  = (const int*)d_in[2];
    float*       out = (float*)d_out;

    int blocks = NPLANES * TILES_PER_PLANE; // 768*14 = 10752
    shake_bilinear_smem_kernel<<<blocks, THREADS>>>(vid, sh, sw, out);
}

// round 5
// speedup vs baseline: 1.2108x; 1.0398x over previous
#include <cuda_runtime.h>
#include <cuda_bf16.h>

// video [B=8, C=3, T=32, H=224, W=224] fp32.
// out[b,c,t,y,x] = clip01( clamped-bilinear sample of frame (b,c,t) at
//   src = (coord + shake + 0.5) * (224/240) - 0.5 )
// (trilinear resize 224->240 has identity T axis; jax boundary weight
//  renormalization for the linear kernel == coordinate clamping.)
//
// R4: separable two-stage smem pipeline.
//  A: coalesced float4 LDG of 16 raw source rows -> sraw
//  B: horizontal lerp once per source row -> hrow (conflict-free scalar LDS,
//     xi/fx computed once per thread, reused over all 16 rows)
//  C: per output: vertical lerp of two ALIGNED float4 LDS from hrow + clip.

#define HH 224
#define WW 224
#define TT 32
#define NPLANES 768                     // B*C*T
#define TILE_Y 16
#define TILES_PER_PLANE (HH / TILE_Y)   // 14
#define THREADS 224
#define SCALE_F (14.0f / 15.0f)

__global__ __launch_bounds__(THREADS) void shake_bilinear_sep_kernel(
    const float* __restrict__ vid,
    const int*   __restrict__ sh,
    const int*   __restrict__ sw,
    float*       __restrict__ out)
{
    __shared__ float sraw[TILE_Y][WW];   // 14336 B
    __shared__ float hrow[TILE_Y][WW];   // 14336 B

    int blk  = blockIdx.x;
    int tile = blk % TILES_PER_PLANE;
    int p    = blk / TILES_PER_PLANE;    // plane = (b*C + c)*T + t
    int t    = p & (TT - 1);
    int sht  = __ldg(sh + t);
    int swt  = __ldg(sw + t);
    int yb   = tile * TILE_Y;
    int tid  = threadIdx.x;

    // Base source row for this tile (may be -1 at the top edge).
    float sy0  = ((float)(yb + sht) + 0.5f) * SCALE_F - 0.5f;
    int   base = (int)floorf(sy0);

    // ---- Stage A: stage 16 clamped source rows (coalesced float4) ----
    const float* plane = vid + (long long)p * (HH * WW);
#pragma unroll
    for (int k = 0; k < 4; k++) {
        int i = tid + k * THREADS;       // 0..895 over 16*56 float4s
        int r = i / (WW / 4);
        int c = i % (WW / 4);
        int srcr = min(max(base + r, 0), HH - 1);
        float4 v = *(const float4*)(plane + srcr * WW + c * 4);
        *(float4*)(&sraw[r][c * 4]) = v;
    }
    __syncthreads();

    // ---- Stage B: horizontal lerp, thread = one x column for all rows ----
    {
        int   x   = tid;                 // 0..223
        float sx  = ((float)(x + swt) + 0.5f) * SCALE_F - 0.5f;
        float f0  = floorf(sx);
        float fx  = sx - f0;
        int   x0  = (int)f0;
        int   x0c = max(x0, 0);
        int   x1c = min(x0 + 1, WW - 1);
#pragma unroll
        for (int r = 0; r < TILE_Y; r++) {
            float s0 = sraw[r][x0c];
            float s1 = sraw[r][x1c];
            hrow[r][x] = fmaf(fx, s1 - s0, s0);
        }
    }
    __syncthreads();

    // ---- Stage C: vertical lerp, aligned float4 LDS x2 per quad ----
    int x4 = tid % (WW / 4);             // 0..55
    int yy = tid / (WW / 4);             // 0..3
    int xb = x4 * 4;

    float4* outp = (float4*)(out + (long long)p * (HH * WW));
#pragma unroll
    for (int k = 0; k < 4; k++) {
        int   y   = yy + 4 * k;          // 0..15
        float sy  = ((float)(yb + y + sht) + 0.5f) * SCALE_F - 0.5f;
        float f0  = floorf(sy);
        float fy  = sy - f0;
        int   r0  = (int)f0 - base;      // in [0,14]; r0+1 <= 15 (clamped rows)

        float4 a = *(const float4*)(&hrow[r0][xb]);
        float4 b = *(const float4*)(&hrow[r0 + 1][xb]);

        float4 res;
        res.x = fminf(fmaxf(fmaf(fy, b.x - a.x, a.x), 0.0f), 1.0f);
        res.y = fminf(fmaxf(fmaf(fy, b.y - a.y, a.y), 0.0f), 1.0f);
        res.z = fminf(fmaxf(fmaf(fy, b.z - a.z, a.z), 0.0f), 1.0f);
        res.w = fminf(fmaxf(fmaf(fy, b.w - a.w, a.w), 0.0f), 1.0f);

        outp[(yb + y) * (WW / 4) + x4] = res;
    }
}

extern "C" void kernel_launch(void* const* d_in, const int* in_sizes, int n_in,
                              void* d_out, int out_size)
{
    const float* vid = (const float*)d_in[0];
    const int*   sh  = (const int*)d_in[1];
    const int*   sw  = (const int*)d_in[2];
    float*       out = (float*)d_out;

    int blocks = NPLANES * TILES_PER_PLANE; // 10752
    shake_bilinear_sep_kernel<<<blocks, THREADS>>>(vid, sh, sw, out);
}